// round 2
// baseline (speedup 1.0000x reference)
#include <cuda_runtime.h>
#include <cuda_bf16.h>
#include <cstdint>

#define N_NODES 50000
#define F_IN    128
#define F_HID   512

// Scratch (allocation-free rule: __device__ globals)
__device__ __align__(16) float g_h0[N_NODES * F_IN];    // (1+eps)*x + agg
__device__ __align__(16) float g_h1[N_NODES * F_HID];   // relu(h0 @ W1 + b1)
__device__ int g_idx_is64;                              // 1 if edge_index is int64

// ---------------------------------------------------------------------------
// Kernel 0: detect edge-index dtype (int64 vs int32).
// For int64 non-negative values < 2^31, every odd 32-bit word is 0.
// For random int32 node ids in [0, 50000), 64 consecutive zeros is impossible.
// ---------------------------------------------------------------------------
__global__ void detect_idx_kernel(const int* __restrict__ ei_words)
{
    int is64 = 1;
    #pragma unroll
    for (int i = 0; i < 64; i++) {
        if (ei_words[2 * i + 1] != 0) { is64 = 0; break; }
    }
    g_idx_is64 = is64;
}

// ---------------------------------------------------------------------------
// Kernel 1: h0 = (1+eps) * x      (vectorized float4)
// ---------------------------------------------------------------------------
__global__ void init_h0_kernel(const float* __restrict__ x,
                               const float* __restrict__ eps,
                               float* __restrict__ h0,
                               int n4)
{
    int i = blockIdx.x * blockDim.x + threadIdx.x;
    if (i >= n4) return;
    float s = 1.0f + *eps;
    float4 v = reinterpret_cast<const float4*>(x)[i];
    v.x *= s; v.y *= s; v.z *= s; v.w *= s;
    reinterpret_cast<float4*>(h0)[i] = v;
}

// ---------------------------------------------------------------------------
// Kernel 2: scatter-add  h0[dst] += x[src]   (one warp per edge, red.v4.f32)
// Edge index dtype resolved at runtime via g_idx_is64 (uniform branch).
// ---------------------------------------------------------------------------
__global__ void scatter_kernel(const float* __restrict__ x,
                               const void* __restrict__ ei,
                               float* __restrict__ h0,
                               int n_edges)
{
    int warps_per_block = blockDim.x >> 5;
    int e = blockIdx.x * warps_per_block + (threadIdx.x >> 5);
    if (e >= n_edges) return;
    int lane = threadIdx.x & 31;

    long long s, d;
    if (g_idx_is64) {
        const long long* p = (const long long*)ei;
        s = p[e];
        d = p[n_edges + e];
    } else {
        const int* p = (const int*)ei;
        s = p[e];
        d = p[n_edges + e];
    }
    // defensive clamp (predicated off in the valid case, costs nothing)
    if (s < 0 || s >= N_NODES || d < 0 || d >= N_NODES) return;

    const float4 v = *reinterpret_cast<const float4*>(x + (size_t)s * F_IN + lane * 4);
    float* p = h0 + (size_t)d * F_IN + lane * 4;
    asm volatile("red.global.add.v4.f32 [%0], {%1,%2,%3,%4};"
                 :: "l"(p), "f"(v.x), "f"(v.y), "f"(v.z), "f"(v.w)
                 : "memory");
}

// ---------------------------------------------------------------------------
// Kernel 3/4: SGEMM  C[M,N] = act(A[M,K] @ B[K,N] + bias)
// 128x128 block tile, BK=8, 256 threads, 8x8 micro-tile per thread.
// A row-major, B row-major, C row-major. N % BN == 0, K % BK == 0 assumed.
// ---------------------------------------------------------------------------
template<int BM, int BN, int BK, bool RELU>
__global__ __launch_bounds__(256)
void sgemm_bias_kernel(const float* __restrict__ A,
                       const float* __restrict__ B,
                       const float* __restrict__ bias,
                       float* __restrict__ C,
                       int M, int N, int K)
{
    __shared__ __align__(16) float As[BK][BM];
    __shared__ __align__(16) float Bs[BK][BN];

    const int tid = threadIdx.x;
    const int bm = blockIdx.y * BM;
    const int bn = blockIdx.x * BN;

    // 8x8 micro-tile position (16x16 thread grid over 128x128 tile)
    const int tr = (tid / (BN / 8)) * 8;
    const int tc = (tid % (BN / 8)) * 8;

    // global->shared load mapping (float4 per thread per tile)
    const int a_row = (tid * 4) / BK;     // 0..BM-1
    const int a_col = (tid * 4) % BK;     // 0 or 4
    const int b_row = (tid * 4) / BN;     // 0..BK-1
    const int b_col = (tid * 4) % BN;

    float acc[8][8];
    #pragma unroll
    for (int i = 0; i < 8; i++)
        #pragma unroll
        for (int j = 0; j < 8; j++)
            acc[i][j] = 0.0f;

    for (int k0 = 0; k0 < K; k0 += BK) {
        // --- load A tile (transposed into As[k][m]) ---
        float4 av;
        const int gr = bm + a_row;
        if (gr < M) {
            av = *reinterpret_cast<const float4*>(A + (size_t)gr * K + k0 + a_col);
        } else {
            av = make_float4(0.f, 0.f, 0.f, 0.f);
        }
        As[a_col + 0][a_row] = av.x;
        As[a_col + 1][a_row] = av.y;
        As[a_col + 2][a_row] = av.z;
        As[a_col + 3][a_row] = av.w;

        // --- load B tile ---
        const float4 bv = *reinterpret_cast<const float4*>(
            B + (size_t)(k0 + b_row) * N + bn + b_col);
        *reinterpret_cast<float4*>(&Bs[b_row][b_col]) = bv;

        __syncthreads();

        #pragma unroll
        for (int k = 0; k < BK; k++) {
            float ra[8], rb[8];
            *reinterpret_cast<float4*>(&ra[0]) = *reinterpret_cast<float4*>(&As[k][tr]);
            *reinterpret_cast<float4*>(&ra[4]) = *reinterpret_cast<float4*>(&As[k][tr + 4]);
            *reinterpret_cast<float4*>(&rb[0]) = *reinterpret_cast<float4*>(&Bs[k][tc]);
            *reinterpret_cast<float4*>(&rb[4]) = *reinterpret_cast<float4*>(&Bs[k][tc + 4]);
            #pragma unroll
            for (int i = 0; i < 8; i++)
                #pragma unroll
                for (int j = 0; j < 8; j++)
                    acc[i][j] = fmaf(ra[i], rb[j], acc[i][j]);
        }
        __syncthreads();
    }

    // --- epilogue: bias (+ relu) + store ---
    #pragma unroll
    for (int i = 0; i < 8; i++) {
        const int gr = bm + tr + i;
        if (gr >= M) break;   // tr..tr+7 contiguous, safe to break
        #pragma unroll
        for (int j = 0; j < 8; j += 4) {
            float4 v;
            v.x = acc[i][j + 0] + bias[bn + tc + j + 0];
            v.y = acc[i][j + 1] + bias[bn + tc + j + 1];
            v.z = acc[i][j + 2] + bias[bn + tc + j + 2];
            v.w = acc[i][j + 3] + bias[bn + tc + j + 3];
            if (RELU) {
                v.x = fmaxf(v.x, 0.f);
                v.y = fmaxf(v.y, 0.f);
                v.z = fmaxf(v.z, 0.f);
                v.w = fmaxf(v.w, 0.f);
            }
            *reinterpret_cast<float4*>(C + (size_t)gr * N + bn + tc + j) = v;
        }
    }
}

// ---------------------------------------------------------------------------
// Launch
// ---------------------------------------------------------------------------
extern "C" void kernel_launch(void* const* d_in, const int* in_sizes, int n_in,
                              void* d_out, int out_size)
{
    const float* x   = (const float*)d_in[0];
    const void*  ei  = d_in[1];
    const float* W1  = (const float*)d_in[2];
    const float* b1  = (const float*)d_in[3];
    const float* W2  = (const float*)d_in[4];
    const float* b2  = (const float*)d_in[5];
    const float* eps = (const float*)d_in[6];
    float* out = (float*)d_out;

    const int n_edges = in_sizes[1] / 2;

    float* h0 = nullptr;
    float* h1 = nullptr;
    cudaGetSymbolAddress((void**)&h0, g_h0);
    cudaGetSymbolAddress((void**)&h1, g_h1);

    // 0) detect edge index dtype
    detect_idx_kernel<<<1, 1>>>((const int*)ei);

    // 1) h0 = (1+eps) * x
    {
        const int n4 = N_NODES * F_IN / 4;
        init_h0_kernel<<<(n4 + 255) / 256, 256>>>(x, eps, h0, n4);
    }

    // 2) h0[dst] += x[src]  (warp per edge)
    {
        const int warps_per_block = 8;            // 256 threads
        const int blocks = (n_edges + warps_per_block - 1) / warps_per_block;
        scatter_kernel<<<blocks, warps_per_block * 32>>>(x, ei, h0, n_edges);
    }

    // 3) h1 = relu(h0 @ W1 + b1)   [50000,128]x[128,512]
    {
        dim3 grid(F_HID / 128, (N_NODES + 127) / 128);
        sgemm_bias_kernel<128, 128, 8, true><<<grid, 256>>>(
            h0, W1, b1, h1, N_NODES, F_HID, F_IN);
    }

    // 4) out = h1 @ W2 + b2        [50000,512]x[512,128]
    {
        dim3 grid(F_IN / 128, (N_NODES + 127) / 128);
        sgemm_bias_kernel<128, 128, 8, false><<<grid, 256>>>(
            h1, W2, b2, out, N_NODES, F_IN, F_HID);
    }
}

// round 4
// speedup vs baseline: 1.7635x; 1.7635x over previous
#include <cuda_runtime.h>
#include <cuda_bf16.h>
#include <cstdint>

#define N_NODES 50000
#define F_IN    128
#define F_HID   512

// ---------------------------------------------------------------------------
// Scratch (__device__ globals; allocation-free rule)
// ---------------------------------------------------------------------------
__device__ __align__(16) float g_h0[N_NODES * F_IN];                  // (1+eps)*x + agg
__device__ __align__(16) __nv_bfloat16 g_h1_hi[N_NODES * F_HID];      // split relu(h0@W1+b1)
__device__ __align__(16) __nv_bfloat16 g_h1_lo[N_NODES * F_HID];
__device__ __align__(16) __nv_bfloat16 g_w1t_hi[F_HID * F_IN];        // W1^T split [512,128]
__device__ __align__(16) __nv_bfloat16 g_w1t_lo[F_HID * F_IN];
__device__ __align__(16) __nv_bfloat16 g_w2t_hi[F_IN * F_HID];        // W2^T split [128,512]
__device__ __align__(16) __nv_bfloat16 g_w2t_lo[F_IN * F_HID];
__device__ int g_idx_is64;

__device__ __forceinline__ uint32_t smem_to_u32(const void* p) {
    uint32_t a;
    asm("{ .reg .u64 t; cvta.to.shared.u64 t, %1; cvt.u32.u64 %0, t; }"
        : "=r"(a) : "l"(p));
    return a;
}
__device__ __forceinline__ uint32_t pack_bf2(__nv_bfloat16 a, __nv_bfloat16 b) {
    __nv_bfloat162 t(a, b);
    return *reinterpret_cast<uint32_t*>(&t);
}
__device__ __forceinline__ uint32_t sw128(uint32_t byte_off) {
    return byte_off ^ ((byte_off >> 3) & 0x70);
}

__device__ __forceinline__ void ldmx4(uint32_t* r, uint32_t addr) {
    asm volatile("ldmatrix.sync.aligned.m8n8.x4.shared.b16 {%0,%1,%2,%3}, [%4];"
                 : "=r"(r[0]), "=r"(r[1]), "=r"(r[2]), "=r"(r[3]) : "r"(addr));
}
__device__ __forceinline__ void ldmx2(uint32_t* r, uint32_t addr) {
    asm volatile("ldmatrix.sync.aligned.m8n8.x2.shared.b16 {%0,%1}, [%2];"
                 : "=r"(r[0]), "=r"(r[1]) : "r"(addr));
}
__device__ __forceinline__ void mma16816(float* c, const uint32_t* a, const uint32_t* b) {
    asm volatile(
        "mma.sync.aligned.m16n8k16.row.col.f32.bf16.bf16.f32 "
        "{%0,%1,%2,%3}, {%4,%5,%6,%7}, {%8,%9}, {%0,%1,%2,%3};"
        : "+f"(c[0]), "+f"(c[1]), "+f"(c[2]), "+f"(c[3])
        : "r"(a[0]), "r"(a[1]), "r"(a[2]), "r"(a[3]), "r"(b[0]), "r"(b[1]));
}

// ---------------------------------------------------------------------------
// Kernel 0: detect edge-index dtype (int64 vs int32).
// ---------------------------------------------------------------------------
__global__ void detect_idx_kernel(const int* __restrict__ ei_words)
{
    int is64 = 1;
    #pragma unroll
    for (int i = 0; i < 64; i++) {
        if (ei_words[2 * i + 1] != 0) { is64 = 0; break; }
    }
    g_idx_is64 = is64;
}

// ---------------------------------------------------------------------------
// Kernel 1: h0 = (1+eps) * x
// ---------------------------------------------------------------------------
__global__ void init_h0_kernel(const float* __restrict__ x,
                               const float* __restrict__ eps,
                               float* __restrict__ h0, int n4)
{
    int i = blockIdx.x * blockDim.x + threadIdx.x;
    if (i >= n4) return;
    float s = 1.0f + *eps;
    float4 v = reinterpret_cast<const float4*>(x)[i];
    v.x *= s; v.y *= s; v.z *= s; v.w *= s;
    reinterpret_cast<float4*>(h0)[i] = v;
}

// ---------------------------------------------------------------------------
// Kernel 2: scatter-add  h0[dst] += x[src]   (warp per edge, red.v4.f32)
// ---------------------------------------------------------------------------
__global__ void scatter_kernel(const float* __restrict__ x,
                               const void* __restrict__ ei,
                               float* __restrict__ h0, int n_edges)
{
    int warps_per_block = blockDim.x >> 5;
    int e = blockIdx.x * warps_per_block + (threadIdx.x >> 5);
    if (e >= n_edges) return;
    int lane = threadIdx.x & 31;

    long long s, d;
    if (g_idx_is64) {
        const long long* p = (const long long*)ei;
        s = p[e]; d = p[n_edges + e];
    } else {
        const int* p = (const int*)ei;
        s = p[e]; d = p[n_edges + e];
    }
    if (s < 0 || s >= N_NODES || d < 0 || d >= N_NODES) return;

    const float4 v = *reinterpret_cast<const float4*>(x + (size_t)s * F_IN + lane * 4);
    float* p = h0 + (size_t)d * F_IN + lane * 4;
    asm volatile("red.global.add.v4.f32 [%0], {%1,%2,%3,%4};"
                 :: "l"(p), "f"(v.x), "f"(v.y), "f"(v.z), "f"(v.w) : "memory");
}

// ---------------------------------------------------------------------------
// Kernel 3: weight transpose + hi/lo bf16 split. out[n*K+k] = split(W[k*N+n]).
// ---------------------------------------------------------------------------
__global__ void transpose_split_kernel(const float* __restrict__ W, int K, int N,
                                       __nv_bfloat16* __restrict__ out_hi,
                                       __nv_bfloat16* __restrict__ out_lo)
{
    int idx = blockIdx.x * blockDim.x + threadIdx.x;
    if (idx >= K * N) return;
    int n = idx / K, k = idx % K;
    float v = W[(size_t)k * N + n];
    __nv_bfloat16 h = __float2bfloat16(v);
    out_hi[idx] = h;
    out_lo[idx] = __float2bfloat16(v - __bfloat162float(h));
}

// ---------------------------------------------------------------------------
// Tensor-core GEMM via mma.sync (bf16 3-pass hi/lo split, fp32 accumulate)
//   C[M, N_total] = act(A[M, K_total] @ Wt^T + bias)
//   A: fp32 (A_F32=true) or pre-split bf16 hi/lo. Wt: pre-split [N_total, K_total].
//   Block tile 128x128, BK=64. 8 warps, warp tile 64x32.
//   SMEM: SW128-swizzled 128B-row tiles; ldmatrix fragments.
//   WRITE_SPLIT: write relu result as bf16 hi/lo (feeds GEMM2); else fp32.
// ---------------------------------------------------------------------------
template<bool A_F32, bool WRITE_SPLIT>
__global__ __launch_bounds__(256, 1)
void gemm_mma_kernel(const float* __restrict__ Af32,
                     const __nv_bfloat16* __restrict__ A_hi,
                     const __nv_bfloat16* __restrict__ A_lo,
                     const __nv_bfloat16* __restrict__ Bt_hi,
                     const __nv_bfloat16* __restrict__ Bt_lo,
                     const float* __restrict__ bias,
                     float* __restrict__ C_f32,
                     __nv_bfloat16* __restrict__ C_hi,
                     __nv_bfloat16* __restrict__ C_lo,
                     int M, int N_total, int K_total)
{
    // SMEM layout: 4 tiles of 128 rows x 64 bf16 (128B rows, SW128 swizzled)
    constexpr int TILE = 128 * 128;   // bytes per tile
    extern __shared__ __align__(1024) char smem[];
    const uint32_t sbase = smem_to_u32(smem);
    const uint32_t sAh = sbase;
    const uint32_t sAl = sbase + TILE;
    const uint32_t sBh = sbase + 2 * TILE;
    const uint32_t sBl = sbase + 3 * TILE;

    const int tid  = threadIdx.x;
    const int wid  = tid >> 5;
    const int lane = tid & 31;
    const int wm   = wid >> 2;          // 0..1  (m half)
    const int wn   = wid & 3;           // 0..3  (n quarter)
    const int bm   = blockIdx.x * 128;
    const int bn   = blockIdx.y * 128;

    float acc[4][4][4];
    #pragma unroll
    for (int i = 0; i < 4; i++)
        #pragma unroll
        for (int j = 0; j < 4; j++)
            #pragma unroll
            for (int q = 0; q < 4; q++)
                acc[i][j][q] = 0.f;

    // Precompute ldmatrix address offsets (within-tile, swizzled at use)
    const int a_row = lane & 15;          // row within 16-row tile
    const int a_kh  = (lane >> 4) & 1;    // k half (x4: 16B)
    const int b_row = lane & 7;           // n within 8
    const int b_kh  = (lane >> 3) & 1;    // k half (x2)

    const int nchunks = K_total >> 6;
    for (int ch = 0; ch < nchunks; ch++) {
        const int k0 = ch << 6;

        // ---- stage A tile (128 x 64) ----
        if (A_F32) {
            #pragma unroll
            for (int it = 0; it < 8; it++) {
                int slot = tid + it * 256;        // 2048 float4 slots
                int r  = slot >> 4;               // 16 float4 per row
                int c4 = slot & 15;               // float4 index
                int gr = bm + r;
                float4 v = (gr < M)
                    ? *reinterpret_cast<const float4*>(Af32 + (size_t)gr * K_total + k0 + c4 * 4)
                    : make_float4(0.f, 0.f, 0.f, 0.f);
                __nv_bfloat16 h0 = __float2bfloat16(v.x);
                __nv_bfloat16 h1 = __float2bfloat16(v.y);
                __nv_bfloat16 h2 = __float2bfloat16(v.z);
                __nv_bfloat16 h3 = __float2bfloat16(v.w);
                uint2 hv, lv;
                hv.x = pack_bf2(h0, h1);
                hv.y = pack_bf2(h2, h3);
                lv.x = pack_bf2(__float2bfloat16(v.x - __bfloat162float(h0)),
                                __float2bfloat16(v.y - __bfloat162float(h1)));
                lv.y = pack_bf2(__float2bfloat16(v.z - __bfloat162float(h2)),
                                __float2bfloat16(v.w - __bfloat162float(h3)));
                uint32_t off = sw128((uint32_t)(r * 128 + c4 * 8));
                *reinterpret_cast<uint2*>(smem + (sAh - sbase) + off) = hv;
                *reinterpret_cast<uint2*>(smem + (sAl - sbase) + off) = lv;
            }
        } else {
            #pragma unroll
            for (int it = 0; it < 4; it++) {
                int slot = tid + it * 256;        // 1024 uint4 slots
                int r  = slot >> 3;               // 8 uint4 per row
                int c8 = slot & 7;
                int gr = bm + r;
                uint4 hv, lv;
                if (gr < M) {
                    hv = *reinterpret_cast<const uint4*>(A_hi + (size_t)gr * K_total + k0 + c8 * 8);
                    lv = *reinterpret_cast<const uint4*>(A_lo + (size_t)gr * K_total + k0 + c8 * 8);
                } else {
                    hv = make_uint4(0, 0, 0, 0); lv = make_uint4(0, 0, 0, 0);
                }
                uint32_t off = sw128((uint32_t)(r * 128 + c8 * 16));
                *reinterpret_cast<uint4*>(smem + (sAh - sbase) + off) = hv;
                *reinterpret_cast<uint4*>(smem + (sAl - sbase) + off) = lv;
            }
        }

        // ---- stage B tile (128 n-rows x 64 k) ----
        #pragma unroll
        for (int it = 0; it < 4; it++) {
            int slot = tid + it * 256;
            int n  = slot >> 3;
            int c8 = slot & 7;
            uint4 hv = *reinterpret_cast<const uint4*>(Bt_hi + (size_t)(bn + n) * K_total + k0 + c8 * 8);
            uint4 lv = *reinterpret_cast<const uint4*>(Bt_lo + (size_t)(bn + n) * K_total + k0 + c8 * 8);
            uint32_t off = sw128((uint32_t)(n * 128 + c8 * 16));
            *reinterpret_cast<uint4*>(smem + (sBh - sbase) + off) = hv;
            *reinterpret_cast<uint4*>(smem + (sBl - sbase) + off) = lv;
        }
        __syncthreads();

        // ---- compute: 4 k16 steps ----
        #pragma unroll
        for (int ks = 0; ks < 4; ks++) {
            uint32_t bh[4][2], bl[4][2];
            #pragma unroll
            for (int nt = 0; nt < 4; nt++) {
                int n  = wn * 32 + nt * 8 + b_row;
                int kb = ks * 32 + b_kh * 16;
                uint32_t off = sw128((uint32_t)(n * 128 + kb));
                ldmx2(bh[nt], sBh + off);
                ldmx2(bl[nt], sBl + off);
            }
            #pragma unroll
            for (int mt = 0; mt < 4; mt++) {
                int m  = wm * 64 + mt * 16 + a_row;
                int kb = ks * 32 + a_kh * 16;
                uint32_t off = sw128((uint32_t)(m * 128 + kb));
                uint32_t ah[4], al[4];
                ldmx4(ah, sAh + off);
                ldmx4(al, sAl + off);
                #pragma unroll
                for (int nt = 0; nt < 4; nt++) {
                    mma16816(acc[mt][nt], ah, bh[nt]);   // hi*hi
                    mma16816(acc[mt][nt], ah, bl[nt]);   // hi*lo
                    mma16816(acc[mt][nt], al, bh[nt]);   // lo*hi
                }
            }
        }
        __syncthreads();
    }

    // ---- epilogue ----
    // thread holds c0=(m, n), c1=(m, n+1), c2=(m+8, n), c3=(m+8, n+1)
    const int er = lane >> 2;
    const int ec = (lane & 3) * 2;
    #pragma unroll
    for (int mt = 0; mt < 4; mt++) {
        const int row0 = bm + wm * 64 + mt * 16 + er;
        #pragma unroll
        for (int nt = 0; nt < 4; nt++) {
            const int col = bn + wn * 32 + nt * 8 + ec;
            const float bia0 = bias[col], bia1 = bias[col + 1];
            #pragma unroll
            for (int h = 0; h < 2; h++) {
                const int row = row0 + h * 8;
                if (row >= M) continue;
                float v0 = acc[mt][nt][2 * h + 0] + bia0;
                float v1 = acc[mt][nt][2 * h + 1] + bia1;
                if (WRITE_SPLIT) {
                    v0 = fmaxf(v0, 0.f);
                    v1 = fmaxf(v1, 0.f);
                    __nv_bfloat16 h0 = __float2bfloat16(v0);
                    __nv_bfloat16 h1 = __float2bfloat16(v1);
                    *reinterpret_cast<uint32_t*>(C_hi + (size_t)row * N_total + col) =
                        pack_bf2(h0, h1);
                    *reinterpret_cast<uint32_t*>(C_lo + (size_t)row * N_total + col) =
                        pack_bf2(__float2bfloat16(v0 - __bfloat162float(h0)),
                                 __float2bfloat16(v1 - __bfloat162float(h1)));
                } else {
                    float2 v; v.x = v0; v.y = v1;
                    *reinterpret_cast<float2*>(C_f32 + (size_t)row * N_total + col) = v;
                }
            }
        }
    }
}

// ---------------------------------------------------------------------------
// Launch
// ---------------------------------------------------------------------------
extern "C" void kernel_launch(void* const* d_in, const int* in_sizes, int n_in,
                              void* d_out, int out_size)
{
    const float* x   = (const float*)d_in[0];
    const void*  ei  = d_in[1];
    const float* W1  = (const float*)d_in[2];
    const float* b1  = (const float*)d_in[3];
    const float* W2  = (const float*)d_in[4];
    const float* b2  = (const float*)d_in[5];
    const float* eps = (const float*)d_in[6];
    float* out = (float*)d_out;

    const int n_edges = in_sizes[1] / 2;

    float *h0; __nv_bfloat16 *h1hi, *h1lo, *w1th, *w1tl, *w2th, *w2tl;
    cudaGetSymbolAddress((void**)&h0,   g_h0);
    cudaGetSymbolAddress((void**)&h1hi, g_h1_hi);
    cudaGetSymbolAddress((void**)&h1lo, g_h1_lo);
    cudaGetSymbolAddress((void**)&w1th, g_w1t_hi);
    cudaGetSymbolAddress((void**)&w1tl, g_w1t_lo);
    cudaGetSymbolAddress((void**)&w2th, g_w2t_hi);
    cudaGetSymbolAddress((void**)&w2tl, g_w2t_lo);

    // 0) dtype detect + weight prep
    detect_idx_kernel<<<1, 1>>>((const int*)ei);
    transpose_split_kernel<<<(F_IN * F_HID + 255) / 256, 256>>>(W1, F_IN, F_HID, w1th, w1tl);
    transpose_split_kernel<<<(F_HID * F_IN + 255) / 256, 256>>>(W2, F_HID, F_IN, w2th, w2tl);

    // 1) h0 = (1+eps) * x
    {
        const int n4 = N_NODES * F_IN / 4;
        init_h0_kernel<<<(n4 + 255) / 256, 256>>>(x, eps, h0, n4);
    }

    // 2) h0[dst] += x[src]
    {
        const int wpb = 8;
        scatter_kernel<<<(n_edges + wpb - 1) / wpb, wpb * 32>>>(x, ei, h0, n_edges);
    }

    const int mtiles = (N_NODES + 127) / 128;   // 391
    constexpr int SMEM = 4 * 128 * 128;         // 64 KB

    // 3) h1(hi/lo bf16) = relu(h0 @ W1 + b1)   [50000,128]x[128,512]
    {
        cudaFuncSetAttribute(gemm_mma_kernel<true, true>,
                             cudaFuncAttributeMaxDynamicSharedMemorySize, SMEM);
        dim3 grid(mtiles, F_HID / 128);
        gemm_mma_kernel<true, true><<<grid, 256, SMEM>>>(
            h0, nullptr, nullptr, w1th, w1tl, b1,
            nullptr, h1hi, h1lo, N_NODES, F_HID, F_IN);
    }

    // 4) out = h1 @ W2 + b2        [50000,512]x[512,128]
    {
        cudaFuncSetAttribute(gemm_mma_kernel<false, false>,
                             cudaFuncAttributeMaxDynamicSharedMemorySize, SMEM);
        dim3 grid(mtiles, F_IN / 128);
        gemm_mma_kernel<false, false><<<grid, 256, SMEM>>>(
            nullptr, h1hi, h1lo, w2th, w2tl, b2,
            out, nullptr, nullptr, N_NODES, F_IN, F_HID);
    }
}

// round 5
// speedup vs baseline: 2.2242x; 1.2612x over previous
#include <cuda_runtime.h>
#include <cuda_bf16.h>
#include <cstdint>

#define N_NODES 50000
#define F_IN    128
#define F_HID   512

// ---------------------------------------------------------------------------
// Scratch (__device__ globals; allocation-free rule)
// ---------------------------------------------------------------------------
__device__ __align__(16) float g_h0[N_NODES * F_IN];                  // (1+eps)*x + agg
__device__ __align__(16) __nv_bfloat16 g_w1t_hi[F_HID * F_IN];        // W1^T split [512,128]
__device__ __align__(16) __nv_bfloat16 g_w1t_lo[F_HID * F_IN];
__device__ __align__(16) __nv_bfloat16 g_w2t_hi[F_IN * F_HID];        // W2^T split [128,512]
__device__ __align__(16) __nv_bfloat16 g_w2t_lo[F_IN * F_HID];
__device__ int g_idx_is64;

__device__ __forceinline__ uint32_t smem_to_u32(const void* p) {
    uint32_t a;
    asm("{ .reg .u64 t; cvta.to.shared.u64 t, %1; cvt.u32.u64 %0, t; }"
        : "=r"(a) : "l"(p));
    return a;
}
__device__ __forceinline__ uint32_t pack_bf2(__nv_bfloat16 a, __nv_bfloat16 b) {
    __nv_bfloat162 t(a, b);
    return *reinterpret_cast<uint32_t*>(&t);
}
__device__ __forceinline__ uint32_t sw128(uint32_t byte_off) {
    return byte_off ^ ((byte_off >> 3) & 0x70);
}
// 128x128 bf16 tile stored as two 128x64 column blocks (16KB each, 128B rows, SW128)
__device__ __forceinline__ uint32_t toff128(int r, int k) {
    return (uint32_t)((k >> 6) * 16384) + sw128((uint32_t)(r * 128 + (k & 63) * 2));
}

__device__ __forceinline__ void ldmx4(uint32_t* r, uint32_t addr) {
    asm volatile("ldmatrix.sync.aligned.m8n8.x4.shared.b16 {%0,%1,%2,%3}, [%4];"
                 : "=r"(r[0]), "=r"(r[1]), "=r"(r[2]), "=r"(r[3]) : "r"(addr));
}
__device__ __forceinline__ void ldmx2(uint32_t* r, uint32_t addr) {
    asm volatile("ldmatrix.sync.aligned.m8n8.x2.shared.b16 {%0,%1}, [%2];"
                 : "=r"(r[0]), "=r"(r[1]) : "r"(addr));
}
__device__ __forceinline__ void mma16816(float* c, const uint32_t* a, const uint32_t* b) {
    asm volatile(
        "mma.sync.aligned.m16n8k16.row.col.f32.bf16.bf16.f32 "
        "{%0,%1,%2,%3}, {%4,%5,%6,%7}, {%8,%9}, {%0,%1,%2,%3};"
        : "+f"(c[0]), "+f"(c[1]), "+f"(c[2]), "+f"(c[3])
        : "r"(a[0]), "r"(a[1]), "r"(a[2]), "r"(a[3]), "r"(b[0]), "r"(b[1]));
}

// ---------------------------------------------------------------------------
// Kernel 0: detect edge-index dtype (int64 vs int32).
// ---------------------------------------------------------------------------
__global__ void detect_idx_kernel(const int* __restrict__ ei_words)
{
    int is64 = 1;
    #pragma unroll
    for (int i = 0; i < 64; i++) {
        if (ei_words[2 * i + 1] != 0) { is64 = 0; break; }
    }
    g_idx_is64 = is64;
}

// ---------------------------------------------------------------------------
// Kernel 1: h0 = (1+eps) * x
// ---------------------------------------------------------------------------
__global__ void init_h0_kernel(const float* __restrict__ x,
                               const float* __restrict__ eps,
                               float* __restrict__ h0, int n4)
{
    int i = blockIdx.x * blockDim.x + threadIdx.x;
    if (i >= n4) return;
    float s = 1.0f + *eps;
    float4 v = reinterpret_cast<const float4*>(x)[i];
    v.x *= s; v.y *= s; v.z *= s; v.w *= s;
    reinterpret_cast<float4*>(h0)[i] = v;
}

// ---------------------------------------------------------------------------
// Kernel 2: scatter-add  h0[dst] += x[src]   (warp per edge, red.v4.f32)
// ---------------------------------------------------------------------------
__global__ void scatter_kernel(const float* __restrict__ x,
                               const void* __restrict__ ei,
                               float* __restrict__ h0, int n_edges)
{
    int warps_per_block = blockDim.x >> 5;
    int e = blockIdx.x * warps_per_block + (threadIdx.x >> 5);
    if (e >= n_edges) return;
    int lane = threadIdx.x & 31;

    long long s, d;
    if (g_idx_is64) {
        const long long* p = (const long long*)ei;
        s = p[e]; d = p[n_edges + e];
    } else {
        const int* p = (const int*)ei;
        s = p[e]; d = p[n_edges + e];
    }
    if (s < 0 || s >= N_NODES || d < 0 || d >= N_NODES) return;

    const float4 v = *reinterpret_cast<const float4*>(x + (size_t)s * F_IN + lane * 4);
    float* p = h0 + (size_t)d * F_IN + lane * 4;
    asm volatile("red.global.add.v4.f32 [%0], {%1,%2,%3,%4};"
                 :: "l"(p), "f"(v.x), "f"(v.y), "f"(v.z), "f"(v.w) : "memory");
}

// ---------------------------------------------------------------------------
// Kernel 3: weight transpose + hi/lo bf16 split. out[n*K+k] = split(W[k*N+n]).
// ---------------------------------------------------------------------------
__global__ void transpose_split_kernel(const float* __restrict__ W, int K, int N,
                                       __nv_bfloat16* __restrict__ out_hi,
                                       __nv_bfloat16* __restrict__ out_lo)
{
    int idx = blockIdx.x * blockDim.x + threadIdx.x;
    if (idx >= K * N) return;
    int n = idx / K, k = idx % K;
    float v = W[(size_t)k * N + n];
    __nv_bfloat16 h = __float2bfloat16(v);
    out_hi[idx] = h;
    out_lo[idx] = __float2bfloat16(v - __bfloat162float(h));
}

// ---------------------------------------------------------------------------
// Fused MLP: out = (relu(h0 @ W1 + b1)) @ W2 + b2, one CTA per 128-row block.
// h1 never leaves SMEM. 4 hidden-chunks of 128:
//   step A: P = h0tile @ W1c (3-pass bf16 split MMA, fp32 acc)
//   step B: bias+relu, split P into SMEM hi/lo
//   step C: out_acc += P @ W2c (3-pass)
// SMEM: A(64K, persistent) | W(64K, W1c then W2c) | H(64K) = 192 KB.
// 256 threads, 8 warps, warp tile 64x32.
// ---------------------------------------------------------------------------
__global__ __launch_bounds__(256, 1)
void fused_mlp_kernel(const float* __restrict__ h0,
                      const __nv_bfloat16* __restrict__ W1t_hi,
                      const __nv_bfloat16* __restrict__ W1t_lo,
                      const float* __restrict__ b1,
                      const __nv_bfloat16* __restrict__ W2t_hi,
                      const __nv_bfloat16* __restrict__ W2t_lo,
                      const float* __restrict__ b2,
                      float* __restrict__ out,
                      int M)
{
    constexpr int SM_A_HI = 0;
    constexpr int SM_A_LO = 32768;
    constexpr int SM_W_HI = 65536;
    constexpr int SM_W_LO = 65536 + 32768;
    constexpr int SM_H_HI = 131072;
    constexpr int SM_H_LO = 131072 + 32768;

    extern __shared__ __align__(1024) char smem[];
    const uint32_t sbase = smem_to_u32(smem);

    const int tid  = threadIdx.x;
    const int wid  = tid >> 5;
    const int lane = tid & 31;
    const int wm   = wid >> 2;          // 0..1
    const int wn   = wid & 3;           // 0..3
    const int bm   = blockIdx.x * 128;

    const int a_row = lane & 15;
    const int a_kh  = (lane >> 4) & 1;
    const int b_row = lane & 7;
    const int b_kh  = (lane >> 3) & 1;
    const int er    = lane >> 2;
    const int ec    = (lane & 3) * 2;

    // ---- stage A = h0 block [128 x 128] fp32 -> split bf16 SMEM (once) ----
    #pragma unroll
    for (int it = 0; it < 16; it++) {
        int slot = tid + it * 256;          // 4096 float4 slots
        int r  = slot >> 5;                 // 32 float4 per row
        int c4 = slot & 31;
        int gr = bm + r;
        float4 v = (gr < M)
            ? *reinterpret_cast<const float4*>(h0 + (size_t)gr * F_IN + c4 * 4)
            : make_float4(0.f, 0.f, 0.f, 0.f);
        __nv_bfloat16 h0b = __float2bfloat16(v.x);
        __nv_bfloat16 h1b = __float2bfloat16(v.y);
        __nv_bfloat16 h2b = __float2bfloat16(v.z);
        __nv_bfloat16 h3b = __float2bfloat16(v.w);
        uint2 hv, lv;
        hv.x = pack_bf2(h0b, h1b);
        hv.y = pack_bf2(h2b, h3b);
        lv.x = pack_bf2(__float2bfloat16(v.x - __bfloat162float(h0b)),
                        __float2bfloat16(v.y - __bfloat162float(h1b)));
        lv.y = pack_bf2(__float2bfloat16(v.z - __bfloat162float(h2b)),
                        __float2bfloat16(v.w - __bfloat162float(h3b)));
        uint32_t off = toff128(r, c4 * 4);
        *reinterpret_cast<uint2*>(smem + SM_A_HI + off) = hv;
        *reinterpret_cast<uint2*>(smem + SM_A_LO + off) = lv;
    }

    float acc_out[4][4][4];
    #pragma unroll
    for (int i = 0; i < 4; i++)
        #pragma unroll
        for (int j = 0; j < 4; j++)
            #pragma unroll
            for (int q = 0; q < 4; q++)
                acc_out[i][j][q] = 0.f;

    for (int c = 0; c < 4; c++) {           // 4 hidden chunks of 128
        // ---- stage W1 chunk [128 hid x 128 k] hi/lo ----
        __syncthreads();                    // W buffer free (prev step C done)
        #pragma unroll
        for (int it = 0; it < 8; it++) {
            int slot = tid + it * 256;      // 2048 uint4 slots
            int r  = slot >> 4;             // 16 uint4 per row
            int c8 = slot & 15;
            size_t g = (size_t)(c * 128 + r) * F_IN + c8 * 8;
            uint32_t off = toff128(r, c8 * 8);
            *reinterpret_cast<uint4*>(smem + SM_W_HI + off) =
                *reinterpret_cast<const uint4*>(W1t_hi + g);
            *reinterpret_cast<uint4*>(smem + SM_W_LO + off) =
                *reinterpret_cast<const uint4*>(W1t_lo + g);
        }
        __syncthreads();

        // ---- step A: P = A @ W1c (3-pass), K = 128 ----
        float acc_h[4][4][4];
        #pragma unroll
        for (int i = 0; i < 4; i++)
            #pragma unroll
            for (int j = 0; j < 4; j++)
                #pragma unroll
                for (int q = 0; q < 4; q++)
                    acc_h[i][j][q] = 0.f;

        #pragma unroll
        for (int ks = 0; ks < 8; ks++) {
            uint32_t bh[4][2], bl[4][2];
            #pragma unroll
            for (int nt = 0; nt < 4; nt++) {
                int n = wn * 32 + nt * 8 + b_row;
                uint32_t off = toff128(n, ks * 16 + b_kh * 8);
                ldmx2(bh[nt], sbase + SM_W_HI + off);
                ldmx2(bl[nt], sbase + SM_W_LO + off);
            }
            #pragma unroll
            for (int mt = 0; mt < 4; mt++) {
                int m = wm * 64 + mt * 16 + a_row;
                uint32_t off = toff128(m, ks * 16 + a_kh * 8);
                uint32_t ah[4], al[4];
                ldmx4(ah, sbase + SM_A_HI + off);
                ldmx4(al, sbase + SM_A_LO + off);
                #pragma unroll
                for (int nt = 0; nt < 4; nt++) {
                    mma16816(acc_h[mt][nt], ah, bh[nt]);
                    mma16816(acc_h[mt][nt], ah, bl[nt]);
                    mma16816(acc_h[mt][nt], al, bh[nt]);
                }
            }
        }
        __syncthreads();                    // all reads of W done -> reuse for W2c

        // ---- step B: bias + relu + split into H; stage W2 chunk ----
        #pragma unroll
        for (int mt = 0; mt < 4; mt++) {
            int lr0 = wm * 64 + mt * 16 + er;
            #pragma unroll
            for (int nt = 0; nt < 4; nt++) {
                int lc = wn * 32 + nt * 8 + ec;
                float bia0 = b1[c * 128 + lc];
                float bia1 = b1[c * 128 + lc + 1];
                #pragma unroll
                for (int h = 0; h < 2; h++) {
                    float v0 = fmaxf(acc_h[mt][nt][2 * h + 0] + bia0, 0.f);
                    float v1 = fmaxf(acc_h[mt][nt][2 * h + 1] + bia1, 0.f);
                    __nv_bfloat16 hh0 = __float2bfloat16(v0);
                    __nv_bfloat16 hh1 = __float2bfloat16(v1);
                    uint32_t off = toff128(lr0 + h * 8, lc);
                    *reinterpret_cast<uint32_t*>(smem + SM_H_HI + off) = pack_bf2(hh0, hh1);
                    *reinterpret_cast<uint32_t*>(smem + SM_H_LO + off) =
                        pack_bf2(__float2bfloat16(v0 - __bfloat162float(hh0)),
                                 __float2bfloat16(v1 - __bfloat162float(hh1)));
                }
            }
        }
        #pragma unroll
        for (int it = 0; it < 8; it++) {
            int slot = tid + it * 256;
            int r  = slot >> 4;             // out-row (n of GEMM2 B operand)
            int c8 = slot & 15;
            size_t g = (size_t)r * F_HID + c * 128 + c8 * 8;
            uint32_t off = toff128(r, c8 * 8);
            *reinterpret_cast<uint4*>(smem + SM_W_HI + off) =
                *reinterpret_cast<const uint4*>(W2t_hi + g);
            *reinterpret_cast<uint4*>(smem + SM_W_LO + off) =
                *reinterpret_cast<const uint4*>(W2t_lo + g);
        }
        __syncthreads();

        // ---- step C: out_acc += H @ W2c (3-pass), K = 128 ----
        #pragma unroll
        for (int ks = 0; ks < 8; ks++) {
            uint32_t bh[4][2], bl[4][2];
            #pragma unroll
            for (int nt = 0; nt < 4; nt++) {
                int n = wn * 32 + nt * 8 + b_row;
                uint32_t off = toff128(n, ks * 16 + b_kh * 8);
                ldmx2(bh[nt], sbase + SM_W_HI + off);
                ldmx2(bl[nt], sbase + SM_W_LO + off);
            }
            #pragma unroll
            for (int mt = 0; mt < 4; mt++) {
                int m = wm * 64 + mt * 16 + a_row;
                uint32_t off = toff128(m, ks * 16 + a_kh * 8);
                uint32_t ah[4], al[4];
                ldmx4(ah, sbase + SM_H_HI + off);
                ldmx4(al, sbase + SM_H_LO + off);
                #pragma unroll
                for (int nt = 0; nt < 4; nt++) {
                    mma16816(acc_out[mt][nt], ah, bh[nt]);
                    mma16816(acc_out[mt][nt], ah, bl[nt]);
                    mma16816(acc_out[mt][nt], al, bh[nt]);
                }
            }
        }
    }

    // ---- epilogue: out + b2, fp32 ----
    #pragma unroll
    for (int mt = 0; mt < 4; mt++) {
        const int row0 = bm + wm * 64 + mt * 16 + er;
        #pragma unroll
        for (int nt = 0; nt < 4; nt++) {
            const int col = wn * 32 + nt * 8 + ec;
            const float bia0 = b2[col], bia1 = b2[col + 1];
            #pragma unroll
            for (int h = 0; h < 2; h++) {
                const int row = row0 + h * 8;
                if (row >= M) continue;
                float2 v;
                v.x = acc_out[mt][nt][2 * h + 0] + bia0;
                v.y = acc_out[mt][nt][2 * h + 1] + bia1;
                *reinterpret_cast<float2*>(out + (size_t)row * F_IN + col) = v;
            }
        }
    }
}

// ---------------------------------------------------------------------------
// Launch
// ---------------------------------------------------------------------------
extern "C" void kernel_launch(void* const* d_in, const int* in_sizes, int n_in,
                              void* d_out, int out_size)
{
    const float* x   = (const float*)d_in[0];
    const void*  ei  = d_in[1];
    const float* W1  = (const float*)d_in[2];
    const float* b1  = (const float*)d_in[3];
    const float* W2  = (const float*)d_in[4];
    const float* b2  = (const float*)d_in[5];
    const float* eps = (const float*)d_in[6];
    float* out = (float*)d_out;

    const int n_edges = in_sizes[1] / 2;

    float *h0; __nv_bfloat16 *w1th, *w1tl, *w2th, *w2tl;
    cudaGetSymbolAddress((void**)&h0,   g_h0);
    cudaGetSymbolAddress((void**)&w1th, g_w1t_hi);
    cudaGetSymbolAddress((void**)&w1tl, g_w1t_lo);
    cudaGetSymbolAddress((void**)&w2th, g_w2t_hi);
    cudaGetSymbolAddress((void**)&w2tl, g_w2t_lo);

    // 0) dtype detect + weight prep
    detect_idx_kernel<<<1, 1>>>((const int*)ei);
    transpose_split_kernel<<<(F_IN * F_HID + 255) / 256, 256>>>(W1, F_IN, F_HID, w1th, w1tl);
    transpose_split_kernel<<<(F_HID * F_IN + 255) / 256, 256>>>(W2, F_HID, F_IN, w2th, w2tl);

    // 1) h0 = (1+eps) * x
    {
        const int n4 = N_NODES * F_IN / 4;
        init_h0_kernel<<<(n4 + 255) / 256, 256>>>(x, eps, h0, n4);
    }

    // 2) h0[dst] += x[src]
    {
        const int wpb = 8;
        scatter_kernel<<<(n_edges + wpb - 1) / wpb, wpb * 32>>>(x, ei, h0, n_edges);
    }

    // 3) fused MLP
    {
        constexpr int SMEM = 196608;   // 192 KB
        cudaFuncSetAttribute(fused_mlp_kernel,
                             cudaFuncAttributeMaxDynamicSharedMemorySize, SMEM);
        const int mtiles = (N_NODES + 127) / 128;   // 391
        fused_mlp_kernel<<<mtiles, 256, SMEM>>>(
            h0, w1th, w1tl, b1, w2th, w2tl, b2, out, N_NODES);
    }
}

// round 6
// speedup vs baseline: 2.3269x; 1.0462x over previous
#include <cuda_runtime.h>
#include <cuda_bf16.h>
#include <cstdint>

#define N_NODES 50000
#define F_IN    128
#define F_HID   512
#define MAX_EDGES 1048576

// ---------------------------------------------------------------------------
// Scratch (__device__ globals; allocation-free rule)
// ---------------------------------------------------------------------------
__device__ __align__(16) float g_h0[N_NODES * F_IN];                  // (1+eps)*x + agg
__device__ __align__(16) __nv_bfloat16 g_w1t_hi[F_HID * F_IN];        // W1^T split [512,128]
__device__ __align__(16) __nv_bfloat16 g_w1t_lo[F_HID * F_IN];
__device__ __align__(16) __nv_bfloat16 g_w2t_hi[F_IN * F_HID];        // W2^T split [128,512]
__device__ __align__(16) __nv_bfloat16 g_w2t_lo[F_IN * F_HID];
__device__ int g_deg[N_NODES];          // in-degree histogram
__device__ int g_off[N_NODES + 1];      // exclusive prefix sum
__device__ int g_cur[N_NODES];          // bucket cursors
__device__ int g_sorted_src[MAX_EDGES]; // src ids bucketed by dst
__device__ int g_idx_is64;

__device__ __forceinline__ uint32_t smem_to_u32(const void* p) {
    uint32_t a;
    asm("{ .reg .u64 t; cvta.to.shared.u64 t, %1; cvt.u32.u64 %0, t; }"
        : "=r"(a) : "l"(p));
    return a;
}
__device__ __forceinline__ uint32_t pack_bf2(__nv_bfloat16 a, __nv_bfloat16 b) {
    __nv_bfloat162 t(a, b);
    return *reinterpret_cast<uint32_t*>(&t);
}
__device__ __forceinline__ uint32_t sw128(uint32_t byte_off) {
    return byte_off ^ ((byte_off >> 3) & 0x70);
}
// 128x128 bf16 tile stored as two 128x64 column blocks (16KB each, 128B rows, SW128)
__device__ __forceinline__ uint32_t toff128(int r, int k) {
    return (uint32_t)((k >> 6) * 16384) + sw128((uint32_t)(r * 128 + (k & 63) * 2));
}

__device__ __forceinline__ void ldmx4(uint32_t* r, uint32_t addr) {
    asm volatile("ldmatrix.sync.aligned.m8n8.x4.shared.b16 {%0,%1,%2,%3}, [%4];"
                 : "=r"(r[0]), "=r"(r[1]), "=r"(r[2]), "=r"(r[3]) : "r"(addr));
}
__device__ __forceinline__ void ldmx2(uint32_t* r, uint32_t addr) {
    asm volatile("ldmatrix.sync.aligned.m8n8.x2.shared.b16 {%0,%1}, [%2];"
                 : "=r"(r[0]), "=r"(r[1]) : "r"(addr));
}
__device__ __forceinline__ void mma16816(float* c, const uint32_t* a, const uint32_t* b) {
    asm volatile(
        "mma.sync.aligned.m16n8k16.row.col.f32.bf16.bf16.f32 "
        "{%0,%1,%2,%3}, {%4,%5,%6,%7}, {%8,%9}, {%0,%1,%2,%3};"
        : "+f"(c[0]), "+f"(c[1]), "+f"(c[2]), "+f"(c[3])
        : "r"(a[0]), "r"(a[1]), "r"(a[2]), "r"(a[3]), "r"(b[0]), "r"(b[1]));
}

// ---------------------------------------------------------------------------
// Edge index accessors (dtype resolved at runtime, uniform branch)
// ---------------------------------------------------------------------------
__device__ __forceinline__ int load_idx(const void* ei, int i) {
    return g_idx_is64 ? (int)((const long long*)ei)[i] : ((const int*)ei)[i];
}

// Kernel 0: detect edge-index dtype (int64 vs int32)
__global__ void detect_idx_kernel(const int* __restrict__ ei_words)
{
    int is64 = 1;
    #pragma unroll
    for (int i = 0; i < 64; i++) {
        if (ei_words[2 * i + 1] != 0) { is64 = 0; break; }
    }
    g_idx_is64 = is64;
}

// Kernel A: zero degree histogram
__global__ void zero_deg_kernel()
{
    int i = blockIdx.x * blockDim.x + threadIdx.x;
    if (i < N_NODES) g_deg[i] = 0;
}

// Kernel B: histogram of dst
__global__ void hist_kernel(const void* __restrict__ ei, int n_edges)
{
    int e = blockIdx.x * blockDim.x + threadIdx.x;
    if (e >= n_edges) return;
    int d = load_idx(ei, n_edges + e);
    if (d >= 0 && d < N_NODES) atomicAdd(&g_deg[d], 1);
}

// Kernel C: single-block exclusive scan of g_deg -> g_off, g_cur
__global__ __launch_bounds__(1024)
void scan_kernel(int n)
{
    __shared__ int warp_sums[32];
    __shared__ int s_carry;
    const int tid  = threadIdx.x;
    const int lane = tid & 31;
    const int wid  = tid >> 5;
    const int nwarps = blockDim.x >> 5;
    if (tid == 0) s_carry = 0;
    __syncthreads();

    for (int base = 0; base < n; base += blockDim.x) {
        int i = base + tid;
        int v = (i < n) ? g_deg[i] : 0;
        int inc = v;
        #pragma unroll
        for (int d = 1; d < 32; d <<= 1) {
            int t = __shfl_up_sync(0xffffffff, inc, d);
            if (lane >= d) inc += t;
        }
        if (lane == 31) warp_sums[wid] = inc;
        __syncthreads();
        if (wid == 0) {
            int ws = (lane < nwarps) ? warp_sums[lane] : 0;
            #pragma unroll
            for (int d = 1; d < 32; d <<= 1) {
                int t = __shfl_up_sync(0xffffffff, ws, d);
                if (lane >= d) ws += t;
            }
            warp_sums[lane] = ws;  // inclusive scan of warp sums
        }
        __syncthreads();
        int warp_off = (wid > 0) ? warp_sums[wid - 1] : 0;
        int excl = s_carry + warp_off + inc - v;
        if (i < n) { g_off[i] = excl; g_cur[i] = excl; }
        __syncthreads();
        if (tid == 0) s_carry += warp_sums[nwarps - 1];
        __syncthreads();
    }
    if (threadIdx.x == 0) g_off[n] = s_carry;
}

// Kernel D: bucket src by dst
__global__ void bucket_kernel(const void* __restrict__ ei, int n_edges)
{
    int e = blockIdx.x * blockDim.x + threadIdx.x;
    if (e >= n_edges) return;
    int s = load_idx(ei, e);
    int d = load_idx(ei, n_edges + e);
    if (s < 0 || s >= N_NODES || d < 0 || d >= N_NODES) return;
    int pos = atomicAdd(&g_cur[d], 1);
    if (pos < MAX_EDGES) g_sorted_src[pos] = s;
}

// Kernel E: gather-accumulate. Warp per node.
//   h0[n] = (1+eps)*x[n] + sum_{e in bucket(n)} x[src[e]]
__global__ void gather_kernel(const float* __restrict__ x,
                              const float* __restrict__ eps,
                              float* __restrict__ h0)
{
    int warp = (blockIdx.x * blockDim.x + threadIdx.x) >> 5;
    if (warp >= N_NODES) return;
    int lane = threadIdx.x & 31;

    const int beg = g_off[warp];
    const int end = g_off[warp + 1];
    const float s = 1.0f + *eps;

    float4 a = *reinterpret_cast<const float4*>(x + (size_t)warp * F_IN + lane * 4);
    float4 acc;
    acc.x = a.x * s; acc.y = a.y * s; acc.z = a.z * s; acc.w = a.w * s;

    int e = beg;
    // unroll by 2 for MLP
    for (; e + 1 < end; e += 2) {
        int s0 = g_sorted_src[e];
        int s1 = g_sorted_src[e + 1];
        float4 v0 = *reinterpret_cast<const float4*>(x + (size_t)s0 * F_IN + lane * 4);
        float4 v1 = *reinterpret_cast<const float4*>(x + (size_t)s1 * F_IN + lane * 4);
        acc.x += v0.x + v1.x; acc.y += v0.y + v1.y;
        acc.z += v0.z + v1.z; acc.w += v0.w + v1.w;
    }
    if (e < end) {
        int s0 = g_sorted_src[e];
        float4 v0 = *reinterpret_cast<const float4*>(x + (size_t)s0 * F_IN + lane * 4);
        acc.x += v0.x; acc.y += v0.y; acc.z += v0.z; acc.w += v0.w;
    }
    *reinterpret_cast<float4*>(h0 + (size_t)warp * F_IN + lane * 4) = acc;
}

// ---------------------------------------------------------------------------
// Kernel 3: weight transpose + hi/lo bf16 split. out[n*K+k] = split(W[k*N+n]).
// ---------------------------------------------------------------------------
__global__ void transpose_split_kernel(const float* __restrict__ W, int K, int N,
                                       __nv_bfloat16* __restrict__ out_hi,
                                       __nv_bfloat16* __restrict__ out_lo)
{
    int idx = blockIdx.x * blockDim.x + threadIdx.x;
    if (idx >= K * N) return;
    int n = idx / K, k = idx % K;
    float v = W[(size_t)k * N + n];
    __nv_bfloat16 h = __float2bfloat16(v);
    out_hi[idx] = h;
    out_lo[idx] = __float2bfloat16(v - __bfloat162float(h));
}

// ---------------------------------------------------------------------------
// Fused MLP: out = (relu(h0 @ W1 + b1)) @ W2 + b2, one CTA per 128-row block.
// (unchanged from R5 — see that round's notes)
// ---------------------------------------------------------------------------
__global__ __launch_bounds__(256, 1)
void fused_mlp_kernel(const float* __restrict__ h0,
                      const __nv_bfloat16* __restrict__ W1t_hi,
                      const __nv_bfloat16* __restrict__ W1t_lo,
                      const float* __restrict__ b1,
                      const __nv_bfloat16* __restrict__ W2t_hi,
                      const __nv_bfloat16* __restrict__ W2t_lo,
                      const float* __restrict__ b2,
                      float* __restrict__ out,
                      int M)
{
    constexpr int SM_A_HI = 0;
    constexpr int SM_A_LO = 32768;
    constexpr int SM_W_HI = 65536;
    constexpr int SM_W_LO = 65536 + 32768;
    constexpr int SM_H_HI = 131072;
    constexpr int SM_H_LO = 131072 + 32768;

    extern __shared__ __align__(1024) char smem[];
    const uint32_t sbase = smem_to_u32(smem);

    const int tid  = threadIdx.x;
    const int wid  = tid >> 5;
    const int lane = tid & 31;
    const int wm   = wid >> 2;
    const int wn   = wid & 3;
    const int bm   = blockIdx.x * 128;

    const int a_row = lane & 15;
    const int a_kh  = (lane >> 4) & 1;
    const int b_row = lane & 7;
    const int b_kh  = (lane >> 3) & 1;
    const int er    = lane >> 2;
    const int ec    = (lane & 3) * 2;

    #pragma unroll
    for (int it = 0; it < 16; it++) {
        int slot = tid + it * 256;
        int r  = slot >> 5;
        int c4 = slot & 31;
        int gr = bm + r;
        float4 v = (gr < M)
            ? *reinterpret_cast<const float4*>(h0 + (size_t)gr * F_IN + c4 * 4)
            : make_float4(0.f, 0.f, 0.f, 0.f);
        __nv_bfloat16 h0b = __float2bfloat16(v.x);
        __nv_bfloat16 h1b = __float2bfloat16(v.y);
        __nv_bfloat16 h2b = __float2bfloat16(v.z);
        __nv_bfloat16 h3b = __float2bfloat16(v.w);
        uint2 hv, lv;
        hv.x = pack_bf2(h0b, h1b);
        hv.y = pack_bf2(h2b, h3b);
        lv.x = pack_bf2(__float2bfloat16(v.x - __bfloat162float(h0b)),
                        __float2bfloat16(v.y - __bfloat162float(h1b)));
        lv.y = pack_bf2(__float2bfloat16(v.z - __bfloat162float(h2b)),
                        __float2bfloat16(v.w - __bfloat162float(h3b)));
        uint32_t off = toff128(r, c4 * 4);
        *reinterpret_cast<uint2*>(smem + SM_A_HI + off) = hv;
        *reinterpret_cast<uint2*>(smem + SM_A_LO + off) = lv;
    }

    float acc_out[4][4][4];
    #pragma unroll
    for (int i = 0; i < 4; i++)
        #pragma unroll
        for (int j = 0; j < 4; j++)
            #pragma unroll
            for (int q = 0; q < 4; q++)
                acc_out[i][j][q] = 0.f;

    for (int c = 0; c < 4; c++) {
        __syncthreads();
        #pragma unroll
        for (int it = 0; it < 8; it++) {
            int slot = tid + it * 256;
            int r  = slot >> 4;
            int c8 = slot & 15;
            size_t g = (size_t)(c * 128 + r) * F_IN + c8 * 8;
            uint32_t off = toff128(r, c8 * 8);
            *reinterpret_cast<uint4*>(smem + SM_W_HI + off) =
                *reinterpret_cast<const uint4*>(W1t_hi + g);
            *reinterpret_cast<uint4*>(smem + SM_W_LO + off) =
                *reinterpret_cast<const uint4*>(W1t_lo + g);
        }
        __syncthreads();

        float acc_h[4][4][4];
        #pragma unroll
        for (int i = 0; i < 4; i++)
            #pragma unroll
            for (int j = 0; j < 4; j++)
                #pragma unroll
                for (int q = 0; q < 4; q++)
                    acc_h[i][j][q] = 0.f;

        #pragma unroll
        for (int ks = 0; ks < 8; ks++) {
            uint32_t bh[4][2], bl[4][2];
            #pragma unroll
            for (int nt = 0; nt < 4; nt++) {
                int n = wn * 32 + nt * 8 + b_row;
                uint32_t off = toff128(n, ks * 16 + b_kh * 8);
                ldmx2(bh[nt], sbase + SM_W_HI + off);
                ldmx2(bl[nt], sbase + SM_W_LO + off);
            }
            #pragma unroll
            for (int mt = 0; mt < 4; mt++) {
                int m = wm * 64 + mt * 16 + a_row;
                uint32_t off = toff128(m, ks * 16 + a_kh * 8);
                uint32_t ah[4], al[4];
                ldmx4(ah, sbase + SM_A_HI + off);
                ldmx4(al, sbase + SM_A_LO + off);
                #pragma unroll
                for (int nt = 0; nt < 4; nt++) {
                    mma16816(acc_h[mt][nt], ah, bh[nt]);
                    mma16816(acc_h[mt][nt], ah, bl[nt]);
                    mma16816(acc_h[mt][nt], al, bh[nt]);
                }
            }
        }
        __syncthreads();

        #pragma unroll
        for (int mt = 0; mt < 4; mt++) {
            int lr0 = wm * 64 + mt * 16 + er;
            #pragma unroll
            for (int nt = 0; nt < 4; nt++) {
                int lc = wn * 32 + nt * 8 + ec;
                float bia0 = b1[c * 128 + lc];
                float bia1 = b1[c * 128 + lc + 1];
                #pragma unroll
                for (int h = 0; h < 2; h++) {
                    float v0 = fmaxf(acc_h[mt][nt][2 * h + 0] + bia0, 0.f);
                    float v1 = fmaxf(acc_h[mt][nt][2 * h + 1] + bia1, 0.f);
                    __nv_bfloat16 hh0 = __float2bfloat16(v0);
                    __nv_bfloat16 hh1 = __float2bfloat16(v1);
                    uint32_t off = toff128(lr0 + h * 8, lc);
                    *reinterpret_cast<uint32_t*>(smem + SM_H_HI + off) = pack_bf2(hh0, hh1);
                    *reinterpret_cast<uint32_t*>(smem + SM_H_LO + off) =
                        pack_bf2(__float2bfloat16(v0 - __bfloat162float(hh0)),
                                 __float2bfloat16(v1 - __bfloat162float(hh1)));
                }
            }
        }
        #pragma unroll
        for (int it = 0; it < 8; it++) {
            int slot = tid + it * 256;
            int r  = slot >> 4;
            int c8 = slot & 15;
            size_t g = (size_t)r * F_HID + c * 128 + c8 * 8;
            uint32_t off = toff128(r, c8 * 8);
            *reinterpret_cast<uint4*>(smem + SM_W_HI + off) =
                *reinterpret_cast<const uint4*>(W2t_hi + g);
            *reinterpret_cast<uint4*>(smem + SM_W_LO + off) =
                *reinterpret_cast<const uint4*>(W2t_lo + g);
        }
        __syncthreads();

        #pragma unroll
        for (int ks = 0; ks < 8; ks++) {
            uint32_t bh[4][2], bl[4][2];
            #pragma unroll
            for (int nt = 0; nt < 4; nt++) {
                int n = wn * 32 + nt * 8 + b_row;
                uint32_t off = toff128(n, ks * 16 + b_kh * 8);
                ldmx2(bh[nt], sbase + SM_W_HI + off);
                ldmx2(bl[nt], sbase + SM_W_LO + off);
            }
            #pragma unroll
            for (int mt = 0; mt < 4; mt++) {
                int m = wm * 64 + mt * 16 + a_row;
                uint32_t off = toff128(m, ks * 16 + a_kh * 8);
                uint32_t ah[4], al[4];
                ldmx4(ah, sbase + SM_H_HI + off);
                ldmx4(al, sbase + SM_H_LO + off);
                #pragma unroll
                for (int nt = 0; nt < 4; nt++) {
                    mma16816(acc_out[mt][nt], ah, bh[nt]);
                    mma16816(acc_out[mt][nt], ah, bl[nt]);
                    mma16816(acc_out[mt][nt], al, bh[nt]);
                }
            }
        }
    }

    #pragma unroll
    for (int mt = 0; mt < 4; mt++) {
        const int row0 = bm + wm * 64 + mt * 16 + er;
        #pragma unroll
        for (int nt = 0; nt < 4; nt++) {
            const int col = wn * 32 + nt * 8 + ec;
            const float bia0 = b2[col], bia1 = b2[col + 1];
            #pragma unroll
            for (int h = 0; h < 2; h++) {
                const int row = row0 + h * 8;
                if (row >= M) continue;
                float2 v;
                v.x = acc_out[mt][nt][2 * h + 0] + bia0;
                v.y = acc_out[mt][nt][2 * h + 1] + bia1;
                *reinterpret_cast<float2*>(out + (size_t)row * F_IN + col) = v;
            }
        }
    }
}

// ---------------------------------------------------------------------------
// Launch
// ---------------------------------------------------------------------------
extern "C" void kernel_launch(void* const* d_in, const int* in_sizes, int n_in,
                              void* d_out, int out_size)
{
    const float* x   = (const float*)d_in[0];
    const void*  ei  = d_in[1];
    const float* W1  = (const float*)d_in[2];
    const float* b1  = (const float*)d_in[3];
    const float* W2  = (const float*)d_in[4];
    const float* b2  = (const float*)d_in[5];
    const float* eps = (const float*)d_in[6];
    float* out = (float*)d_out;

    const int n_edges = in_sizes[1] / 2;

    float *h0; __nv_bfloat16 *w1th, *w1tl, *w2th, *w2tl;
    cudaGetSymbolAddress((void**)&h0,   g_h0);
    cudaGetSymbolAddress((void**)&w1th, g_w1t_hi);
    cudaGetSymbolAddress((void**)&w1tl, g_w1t_lo);
    cudaGetSymbolAddress((void**)&w2th, g_w2t_hi);
    cudaGetSymbolAddress((void**)&w2tl, g_w2t_lo);

    // 0) dtype detect + weight prep + degree zero (independent work first)
    detect_idx_kernel<<<1, 1>>>((const int*)ei);
    zero_deg_kernel<<<(N_NODES + 255) / 256, 256>>>();
    transpose_split_kernel<<<(F_IN * F_HID + 255) / 256, 256>>>(W1, F_IN, F_HID, w1th, w1tl);
    transpose_split_kernel<<<(F_HID * F_IN + 255) / 256, 256>>>(W2, F_HID, F_IN, w2th, w2tl);

    // 1) counting sort of edges by dst
    hist_kernel<<<(n_edges + 255) / 256, 256>>>(ei, n_edges);
    scan_kernel<<<1, 1024>>>(N_NODES);
    bucket_kernel<<<(n_edges + 255) / 256, 256>>>(ei, n_edges);

    // 2) gather-accumulate (fuses (1+eps)*x init)
    {
        const int warps = N_NODES;
        const int wpb = 8;  // 256 threads
        gather_kernel<<<(warps + wpb - 1) / wpb, wpb * 32>>>(x, eps, h0);
    }

    // 3) fused MLP
    {
        constexpr int SMEM = 196608;   // 192 KB
        cudaFuncSetAttribute(fused_mlp_kernel,
                             cudaFuncAttributeMaxDynamicSharedMemorySize, SMEM);
        const int mtiles = (N_NODES + 127) / 128;   // 391
        fused_mlp_kernel<<<mtiles, 256, SMEM>>>(
            h0, w1th, w1tl, b1, w2th, w2tl, b2, out, N_NODES);
    }
}